// round 2
// baseline (speedup 1.0000x reference)
#include <cuda_runtime.h>
#include <math.h>

// Problem constants
#define Bb   8
#define Ss   256
#define Nn   512
#define Ii   32
#define HH   64
#define Oo   32
#define BS   (Bb*Ss)                 // 2048
#define RTOT (BS*Nn)                 // 1,048,576 rows
#define BN   (Bb*Nn)                 // 4096 GRU sequences

// Scratch (device globals; allocation-free kernel_launch)
__device__ float g_sp  [(size_t)RTOT * Oo];   // 134 MB: GCN2 output (pre-adj)
__device__ float g_tanh[(size_t)RTOT * Oo];   // 134 MB: tanh(adj @ sp)
__device__ float g_gi  [(size_t)RTOT * 96];   // 402 MB: GRU input gates

__device__ __forceinline__ float warp_sum(float v) {
    #pragma unroll
    for (int o = 16; o > 0; o >>= 1) v += __shfl_xor_sync(0xffffffffu, v, o);
    return v;
}
__device__ __forceinline__ float sigmoid_f(float x) {
    return __fdividef(1.f, 1.f + __expf(-x));
}
__device__ __forceinline__ float tanh_f(float x) {
    float ax = fabsf(x);
    float e  = __expf(-2.f * ax);
    float t  = (1.f - e) * __fdividef(1.f, 1.f + e);
    return copysignf(t, x);
}

// ---------------------------------------------------------------------------
// K1: per row r (of RTOT): t = x@W1+b1 ; h = relu(LN64(t)) ; sp = h@W2+b2+x
// Warp handles 4 rows. Weights staged in smem as interleaved pairs so each
// jj/kk step is one LDS.64 per thread.
// ---------------------------------------------------------------------------
__global__ __launch_bounds__(256) void k1_gcn(
    const float* __restrict__ x,  const float* __restrict__ W1,
    const float* __restrict__ b1, const float* __restrict__ g1,
    const float* __restrict__ be1,const float* __restrict__ W2,
    const float* __restrict__ b2, float* __restrict__ sp_out)
{
    __shared__ __align__(16) float W1p[2048];  // [jj][j][p]: (W1[jj][j], W1[jj][j+32])
    __shared__ __align__(16) float W2p[2048];  // [kk][j][p]: (W2[kk][j], W2[kk+32][j])
    __shared__ float b1s[64], g1s[64], be1s[64], b2s[32];

    int tid = threadIdx.x;
    for (int i = tid; i < 2048; i += 256) {
        int jj = i >> 6, rem = i & 63, j = rem >> 1, p = rem & 1;
        W1p[i] = W1[jj * 64 + j + p * 32];
        W2p[i] = W2[(jj + p * 32) * 32 + j];
    }
    if (tid < 64) { b1s[tid] = b1[tid]; g1s[tid] = g1[tid]; be1s[tid] = be1[tid]; }
    if (tid < 32) b2s[tid] = b2[tid];
    __syncthreads();

    int lane = tid & 31;
    size_t r0 = ((size_t)blockIdx.x * 8 + (tid >> 5)) * 4;

    float xv[4], t0[4], t1[4];
    #pragma unroll
    for (int q = 0; q < 4; q++) {
        xv[q] = x[(r0 + q) * 32 + lane];
        t0[q] = b1s[lane]; t1[q] = b1s[lane + 32];
    }
    #pragma unroll
    for (int jj = 0; jj < 32; jj++) {
        float2 w = *(const float2*)&W1p[jj * 64 + lane * 2];
        #pragma unroll
        for (int q = 0; q < 4; q++) {
            float xb = __shfl_sync(0xffffffffu, xv[q], jj);
            t0[q] = fmaf(xb, w.x, t0[q]);
            t1[q] = fmaf(xb, w.y, t1[q]);
        }
    }
    float h0[4], h1[4];
    #pragma unroll
    for (int q = 0; q < 4; q++) {
        float mu = warp_sum(t0[q] + t1[q]) * (1.f / 64.f);
        float d0 = t0[q] - mu, d1 = t1[q] - mu;
        float var = warp_sum(d0 * d0 + d1 * d1) * (1.f / 64.f);
        float rstd = rsqrtf(var + 1e-5f);
        h0[q] = fmaxf(fmaf(d0 * rstd, g1s[lane],      be1s[lane]),      0.f);
        h1[q] = fmaxf(fmaf(d1 * rstd, g1s[lane + 32], be1s[lane + 32]), 0.f);
    }
    float sp[4];
    #pragma unroll
    for (int q = 0; q < 4; q++) sp[q] = b2s[lane] + xv[q];
    #pragma unroll
    for (int kk = 0; kk < 32; kk++) {
        float2 w = *(const float2*)&W2p[kk * 64 + lane * 2];
        #pragma unroll
        for (int q = 0; q < 4; q++) {
            float a = __shfl_sync(0xffffffffu, h0[q], kk);
            float b = __shfl_sync(0xffffffffu, h1[q], kk);
            sp[q] = fmaf(a, w.x, fmaf(b, w.y, sp[q]));
        }
    }
    #pragma unroll
    for (int q = 0; q < 4; q++) sp_out[(r0 + q) * 32 + lane] = sp[q];
}

// ---------------------------------------------------------------------------
// K2: out[bs,n,f] = tanh( sum_m adj[n,m] * sp[bs,m,f] )
// Block: 256 threads, tile C[128 n][32 f], 4x4 register blocking, m-chunks of 32.
// ---------------------------------------------------------------------------
__global__ __launch_bounds__(256) void k2_adj(
    const float* __restrict__ adj, const float* __restrict__ sp,
    float* __restrict__ out)
{
    __shared__ __align__(16) float adjs[128 * 33];
    __shared__ __align__(16) float sps [32 * 32];

    int bs  = blockIdx.y;
    int n0  = blockIdx.x * 128;
    int tid = threadIdx.x;
    int fbase = (tid & 7) * 4;
    int nbase = (tid >> 3) * 4;
    const float* spb = sp + (size_t)bs * (Nn * Oo);

    float c[4][4] = {};
    for (int mc = 0; mc < 512; mc += 32) {
        __syncthreads();
        {
            int m4 = (tid & 7) * 4;
            int nl = tid >> 3;  // 0..31
            #pragma unroll
            for (int rep = 0; rep < 4; rep++) {
                int nn = nl + rep * 32;
                float4 v = *(const float4*)&adj[(size_t)(n0 + nn) * 512 + mc + m4];
                adjs[nn * 33 + m4 + 0] = v.x;
                adjs[nn * 33 + m4 + 1] = v.y;
                adjs[nn * 33 + m4 + 2] = v.z;
                adjs[nn * 33 + m4 + 3] = v.w;
            }
            float4 v = *(const float4*)&spb[(size_t)(mc + nl) * 32 + m4];
            *(float4*)&sps[nl * 32 + m4] = v;
        }
        __syncthreads();
        #pragma unroll
        for (int mm = 0; mm < 32; mm++) {
            float4 bv = *(const float4*)&sps[mm * 32 + fbase];
            float a0 = adjs[(nbase + 0) * 33 + mm];
            float a1 = adjs[(nbase + 1) * 33 + mm];
            float a2 = adjs[(nbase + 2) * 33 + mm];
            float a3 = adjs[(nbase + 3) * 33 + mm];
            c[0][0] = fmaf(a0, bv.x, c[0][0]); c[0][1] = fmaf(a0, bv.y, c[0][1]);
            c[0][2] = fmaf(a0, bv.z, c[0][2]); c[0][3] = fmaf(a0, bv.w, c[0][3]);
            c[1][0] = fmaf(a1, bv.x, c[1][0]); c[1][1] = fmaf(a1, bv.y, c[1][1]);
            c[1][2] = fmaf(a1, bv.z, c[1][2]); c[1][3] = fmaf(a1, bv.w, c[1][3]);
            c[2][0] = fmaf(a2, bv.x, c[2][0]); c[2][1] = fmaf(a2, bv.y, c[2][1]);
            c[2][2] = fmaf(a2, bv.z, c[2][2]); c[2][3] = fmaf(a2, bv.w, c[2][3]);
            c[3][0] = fmaf(a3, bv.x, c[3][0]); c[3][1] = fmaf(a3, bv.y, c[3][1]);
            c[3][2] = fmaf(a3, bv.z, c[3][2]); c[3][3] = fmaf(a3, bv.w, c[3][3]);
        }
    }
    #pragma unroll
    for (int i = 0; i < 4; i++) {
        size_t base = ((size_t)bs * 512 + n0 + nbase + i) * 32 + fbase;
        #pragma unroll
        for (int j = 0; j < 4; j++) out[base + j] = tanhf(c[i][j]);
    }
}

// ---------------------------------------------------------------------------
// K3: LN over O=32 per row, then gi = ln @ w_ih^T + b_ih written in GRU order.
// Warp handles 4 rows; w_ih transposed into [jj][j][4] float4 layout in smem.
// ---------------------------------------------------------------------------
__global__ __launch_bounds__(256) void k3_ln_gi(
    const float* __restrict__ tin, const float* __restrict__ g2,
    const float* __restrict__ be2, const float* __restrict__ w_ih,
    const float* __restrict__ b_ih, float* __restrict__ gi)
{
    __shared__ __align__(16) float wT[32 * 128]; // [jj][j][p], p<3 = w_ih[(j+p*32)*32+jj]
    int tid = threadIdx.x;
    for (int i = tid; i < 4096; i += 256) {
        int jj = i >> 7, rem = i & 127, j = rem >> 2, p = rem & 3;
        wT[i] = (p < 3) ? w_ih[(j + p * 32) * 32 + jj] : 0.f;
    }
    __syncthreads();

    int lane = tid & 31;
    size_t r0 = ((size_t)blockIdx.x * 8 + (tid >> 5)) * 4;
    float g2v = g2[lane], be2v = be2[lane];
    float bi0 = b_ih[lane], bi1 = b_ih[lane + 32], bi2 = b_ih[lane + 64];

    float ln[4], acc0[4], acc1[4], acc2[4];
    #pragma unroll
    for (int q = 0; q < 4; q++) {
        float v = tin[(r0 + q) * 32 + lane];
        float mu = warp_sum(v) * (1.f / 32.f);
        float d = v - mu;
        float var = warp_sum(d * d) * (1.f / 32.f);
        ln[q] = fmaf(d * rsqrtf(var + 1e-5f), g2v, be2v);
        acc0[q] = bi0; acc1[q] = bi1; acc2[q] = bi2;
    }
    #pragma unroll
    for (int jj = 0; jj < 32; jj++) {
        float4 w = *(const float4*)&wT[jj * 128 + lane * 4];
        #pragma unroll
        for (int q = 0; q < 4; q++) {
            float lv = __shfl_sync(0xffffffffu, ln[q], jj);
            acc0[q] = fmaf(lv, w.x, acc0[q]);
            acc1[q] = fmaf(lv, w.y, acc1[q]);
            acc2[q] = fmaf(lv, w.z, acc2[q]);
        }
    }
    #pragma unroll
    for (int q = 0; q < 4; q++) {
        size_t r = r0 + q;
        int b = (int)(r >> 17);              // / (S*N)
        int s = (int)((r >> 9) & 255);       // / N % S
        int n = (int)(r & 511);
        size_t base = ((size_t)(b * 512 + n) * 256 + s) * 96;
        gi[base + lane]      = acc0[q];
        gi[base + lane + 32] = acc1[q];
        gi[base + lane + 64] = acc2[q];
    }
}

// ---------------------------------------------------------------------------
// K4: GRU scan. One warp per (b,n) sequence; h lives in registers, w_hh rows
// in registers (96/thread), broadcast h via shuffles. 256 steps, no grid sync.
// ---------------------------------------------------------------------------
__global__ __launch_bounds__(256) void k4_gru(
    const float* __restrict__ gi, const float* __restrict__ w_hh,
    const float* __restrict__ b_hh, float* __restrict__ out)
{
    int tid = threadIdx.x, lane = tid & 31;
    int bn = blockIdx.x * 8 + (tid >> 5);
    int b = bn >> 9, n = bn & 511;

    float w0[32], w1[32], w2[32];
    #pragma unroll
    for (int m = 0; m < 8; m++) {
        float4 a = ((const float4*)(w_hh + (size_t)lane * 32))[m];
        float4 c = ((const float4*)(w_hh + (size_t)(lane + 32) * 32))[m];
        float4 d = ((const float4*)(w_hh + (size_t)(lane + 64) * 32))[m];
        w0[4*m+0]=a.x; w0[4*m+1]=a.y; w0[4*m+2]=a.z; w0[4*m+3]=a.w;
        w1[4*m+0]=c.x; w1[4*m+1]=c.y; w1[4*m+2]=c.z; w1[4*m+3]=c.w;
        w2[4*m+0]=d.x; w2[4*m+1]=d.y; w2[4*m+2]=d.z; w2[4*m+3]=d.w;
    }
    float bh0 = b_hh[lane], bh1 = b_hh[lane + 32], bh2 = b_hh[lane + 64];

    float h = 0.f;
    const float* gp = gi + (size_t)bn * 256 * 96;
    for (int t = 0; t < 256; t++, gp += 96) {
        float q0 = gp[lane], q1 = gp[lane + 32], q2 = gp[lane + 64];
        float a0 = bh0, a1 = bh1, a2 = bh2;
        #pragma unroll
        for (int jj = 0; jj < 32; jj++) {
            float hv = __shfl_sync(0xffffffffu, h, jj);
            a0 = fmaf(hv, w0[jj], a0);
            a1 = fmaf(hv, w1[jj], a1);
            a2 = fmaf(hv, w2[jj], a2);
        }
        float rg = sigmoid_f(q0 + a0);
        float zg = sigmoid_f(q1 + a1);
        float ng = tanh_f(fmaf(rg, a2, q2));
        h = fmaf(zg, h - ng, ng);   // (1-z)*n + z*h
        out[((size_t)(b * 256 + t) * 512 + n) * 32 + lane] = h;
    }
}

// ---------------------------------------------------------------------------
extern "C" void kernel_launch(void* const* d_in, const int* in_sizes, int n_in,
                              void* d_out, int out_size)
{
    (void)in_sizes; (void)n_in; (void)out_size;
    const float* x    = (const float*)d_in[0];
    const float* adj  = (const float*)d_in[1];
    const float* W1   = (const float*)d_in[2];
    const float* b1   = (const float*)d_in[3];
    const float* g1   = (const float*)d_in[4];
    const float* be1  = (const float*)d_in[5];
    const float* W2   = (const float*)d_in[6];
    const float* b2   = (const float*)d_in[7];
    const float* g2   = (const float*)d_in[8];
    const float* be2  = (const float*)d_in[9];
    const float* w_ih = (const float*)d_in[10];
    const float* w_hh = (const float*)d_in[11];
    const float* b_ih = (const float*)d_in[12];
    const float* b_hh = (const float*)d_in[13];
    float* out = (float*)d_out;

    float *sp, *th, *gi;
    cudaGetSymbolAddress((void**)&sp, g_sp);
    cudaGetSymbolAddress((void**)&th, g_tanh);
    cudaGetSymbolAddress((void**)&gi, g_gi);

    // K1: 1,048,576 rows / (8 warps * 4 rows) = 32768 blocks
    k1_gcn<<<RTOT / 32, 256>>>(x, W1, b1, g1, be1, W2, b2, sp);
    // K2: 2048 batches x 4 n-tiles
    k2_adj<<<dim3(4, BS), 256>>>(adj, sp, th);
    // K3: same row decomposition as K1
    k3_ln_gi<<<RTOT / 32, 256>>>(th, g2, be2, w_ih, b_ih, gi);
    // K4: 4096 sequences / 8 warps = 512 blocks
    k4_gru<<<BN / 8, 256>>>(gi, w_hh, b_hh, out);
}